// round 9
// baseline (speedup 1.0000x reference)
#include <cuda_runtime.h>
#include <math_constants.h>

// FusedScaleMaskSoftmax: x[2,16,2048,2048] fp32 -> causal-masked softmax (last dim).
//
// R8: two-phase split retained (R7):
//   Kernel A: pure-write zero-fill of all fully-masked 32B chunks.
//   Kernel B: softmax over the causal prefix (256-bit ld/st, warp-shuffle sum).
// Changes vs R7:
//   - stores use default .wb policy (was .cs): let L2 accumulate full dirty
//     lines and schedule writebacks in large bursts instead of evict-first
//     streaming stores. Loads stay .cs to keep read stream from evicting
//     pending dirty write lines.
//   - 256-thread blocks (8 rows/CTA): half the CTA count, fewer wave
//     transitions, tighter packing of the fractional final wave.
// Traffic remains at the causal floor: 256MB read + 512MB write.

#define SK        2048
#define THREADS   256            // 8 warps = 8 rows per block
#define WARPS_PB  (THREADS / 32)
#define NC        8              // 256-bit chunks per lane in kernel B
#define NCHUNKS   (SK / 8)       // 256 chunks per row

__device__ __forceinline__ float ex2_approx(float x) {
    float r;
    asm("ex2.approx.ftz.f32 %0, %1;" : "=f"(r) : "f"(x));
    return r;
}

__device__ __forceinline__ void ldg256_cs(const float* p, float* v) {
    unsigned u0, u1, u2, u3, u4, u5, u6, u7;
    asm volatile("ld.global.cs.v8.b32 {%0,%1,%2,%3,%4,%5,%6,%7}, [%8];"
        : "=r"(u0), "=r"(u1), "=r"(u2), "=r"(u3),
          "=r"(u4), "=r"(u5), "=r"(u6), "=r"(u7)
        : "l"(p));
    v[0] = __uint_as_float(u0); v[1] = __uint_as_float(u1);
    v[2] = __uint_as_float(u2); v[3] = __uint_as_float(u3);
    v[4] = __uint_as_float(u4); v[5] = __uint_as_float(u5);
    v[6] = __uint_as_float(u6); v[7] = __uint_as_float(u7);
}

// Default write-back policy stores (no .cs).
__device__ __forceinline__ void stg256(float* p, const float* v) {
    asm volatile("st.global.v8.b32 [%0], {%1,%2,%3,%4,%5,%6,%7,%8};"
        :: "l"(p),
           "r"(__float_as_uint(v[0])), "r"(__float_as_uint(v[1])),
           "r"(__float_as_uint(v[2])), "r"(__float_as_uint(v[3])),
           "r"(__float_as_uint(v[4])), "r"(__float_as_uint(v[5])),
           "r"(__float_as_uint(v[6])), "r"(__float_as_uint(v[7]))
        : "memory");
}

// Balanced row mapping: pair j with 2047-j within each 2048-row matrix.
__device__ __forceinline__ unsigned map_row(unsigned g) {
    const unsigned q = g & (SK - 1);
    const unsigned j = q >> 1;
    const unsigned r = (q & 1u) ? (SK - 1 - j) : j;
    return (g & ~(unsigned)(SK - 1)) | r;
}

// ---------------- Kernel A: pure-write zero-fill of masked chunks ----------------
__global__ __launch_bounds__(THREADS)
void causal_zero_tail(float* __restrict__ out) {
    const int wid = threadIdx.x >> 5;
    const int lid = threadIdx.x & 31;

    const unsigned g   = blockIdx.x * WARPS_PB + wid;
    const unsigned row = map_row(g);
    const int L  = (int)(row & (SK - 1)) + 1;
    const int c0 = (L + 7) >> 3;          // first fully-masked chunk

    float* __restrict__ yrow = out + (size_t)row * SK;
    const float z[8] = {0.f, 0.f, 0.f, 0.f, 0.f, 0.f, 0.f, 0.f};

    // Consecutive lanes write consecutive 32B chunks -> 1KB per warp instr.
    for (int c = c0 + lid; c < NCHUNKS; c += 32)
        stg256(yrow + (c << 3), z);
}

// ---------------- Kernel B: softmax over the causal prefix ----------------
__global__ __launch_bounds__(THREADS)
void causal_softmax_prefix(const float* __restrict__ x,
                           float* __restrict__ out) {
    // SCALE * log2(e): fold 1/sqrt(128) into the exp2 argument.
    const float C = 0.08838834764831845f * 1.4426950408889634f;

    const int wid = threadIdx.x >> 5;
    const int lid = threadIdx.x & 31;

    const unsigned g   = blockIdx.x * WARPS_PB + wid;
    const unsigned row = map_row(g);
    const int L = (int)(row & (SK - 1)) + 1;

    const size_t base_elem = (size_t)row * SK;
    const float* __restrict__ xrow = x   + base_elem;
    float* __restrict__       yrow = out + base_elem;

    float v[NC][8];

    // Front-batched 256-bit loads of valid chunks (8c < L).
    #pragma unroll
    for (int k = 0; k < NC; k++) {
        const int b = (lid + k * 32) << 3;
        if (b < L) ldg256_cs(xrow + b, v[k]);
    }

    // exp2(x*C) with per-lane mask (partial chunk tail lanes -> exact 0).
    float s = 0.0f;
    #pragma unroll
    for (int k = 0; k < NC; k++) {
        const int b = (lid + k * 32) << 3;
        if (b < L) {
            float a[8];
            #pragma unroll
            for (int e = 0; e < 8; e++)
                a[e] = (b + e < L) ? ex2_approx(v[k][e] * C) : 0.0f;
            #pragma unroll
            for (int e = 0; e < 8; e++)
                v[k][e] = a[e];
            s += ((a[0] + a[1]) + (a[2] + a[3]))
               + ((a[4] + a[5]) + (a[6] + a[7]));
        }
    }

    // Warp sum-reduce (no barriers).
    #pragma unroll
    for (int o = 16; o > 0; o >>= 1)
        s += __shfl_xor_sync(0xffffffffu, s, o);

    float inv;
    asm("rcp.approx.ftz.f32 %0, %1;" : "=f"(inv) : "f"(s));

    // Normalize + 256-bit store of valid chunks only.
    #pragma unroll
    for (int k = 0; k < NC; k++) {
        const int b = (lid + k * 32) << 3;
        if (b < L) {
            float o[8];
            #pragma unroll
            for (int e = 0; e < 8; e++)
                o[e] = v[k][e] * inv;
            stg256(yrow + b, o);
        }
    }
}

extern "C" void kernel_launch(void* const* d_in, const int* in_sizes, int n_in,
                              void* d_out, int out_size) {
    const float* x = (const float*)d_in[0];
    float* out = (float*)d_out;

    const int rows   = out_size / SK;          // 65536
    const int blocks = rows / WARPS_PB;        // 8192

    // Phase 1: pure-write burst (masked chunks).
    causal_zero_tail<<<blocks, THREADS>>>(out);
    // Phase 2: read+write over valid prefix (disjoint chunks).
    causal_softmax_prefix<<<blocks, THREADS>>>(x, out);
}